// round 2
// baseline (speedup 1.0000x reference)
#include <cuda_runtime.h>

// Problem constants
#define B_DIM 8
#define D_DIM 40
#define H_DIM 32
#define W_DIM 88
#define C_DIM 80
#define NX 256
#define NY 256
// NZ = 1, iz always 0 for in-bounds points

// ---------------------------------------------------------------------------
// Zero the 168 MB output (poisoned to 0xAA by the harness).
// ---------------------------------------------------------------------------
__global__ void zero_kernel(float4* __restrict__ out, int n4) {
    int i = blockIdx.x * blockDim.x + threadIdx.x;
    if (i < n4) out[i] = make_float4(0.f, 0.f, 0.f, 0.f);
}

// ---------------------------------------------------------------------------
// Scatter kernel: one block per (b, d, h) row of W=88 points.
// Phase 1: threads 0..87 compute the flat BEV cell index per point (or -1)
//          into shared memory — geom read exactly once per point.
// Phase 2: block loops over C*W = 7040 elements; consecutive threads read
//          consecutive w of x[b,d,c,h,:] (coalesced), then RED.ADD into
//          out[((b*C)+c)*65536 + flat].
// ---------------------------------------------------------------------------
__global__ void __launch_bounds__(256) scatter_kernel(
    const float* __restrict__ geom,   // (B, D, H, W, 3)
    const float* __restrict__ x,      // (B, D, C, H, W)
    float* __restrict__ out)          // (B, C, NX, NY) since NZ=1
{
    __shared__ int s_flat[W_DIM];

    const int bid = blockIdx.x;           // 0 .. B*D*H-1
    const int h   = bid % H_DIM;
    const int bd  = bid / H_DIM;
    const int d   = bd % D_DIM;
    const int b   = bd / D_DIM;

    const int t = threadIdx.x;

    if (t < W_DIM) {
        // geom row base: ((b*D + d)*H + h)*W + w, times 3 floats
        const float* g = geom + ((long long)bid * W_DIM + t) * 3;
        const float gx = g[0];
        const float gy = g[1];
        const float gz = g[2];

        int flat = -1;
        // Exact replication of reference bounds test (float32 compares)
        if (gx >= -51.2f && gx < 51.2f &&
            gy >= -51.2f && gy < 51.2f &&
            gz >= -10.0f && gz < 10.0f) {
            // Reference computes ((g - lo) / dd).astype(int32) with clip.
            // XLA rewrites div-by-const as mul-by-reciprocal: 1/0.4f == 2.5f
            // exactly in fp32. Use the same mul to match bin edges bit-exactly.
            // (add-then-mul cannot be FMA-contracted, so this stays a MUL.)
            const float rx = (gx + 51.2f) * 2.5f;
            const float ry = (gy + 51.2f) * 2.5f;
            int ix = (int)rx;
            int iy = (int)ry;
            ix = min(max(ix, 0), NX - 1);
            iy = min(max(iy, 0), NY - 1);
            flat = ix * NY + iy;
        }
        s_flat[t] = flat;
    }
    __syncthreads();

    // x base for this (b, d, *, h, *): index (((b*D+d)*C + c)*H + h)*W + w
    const long long x_base = (((long long)(b * D_DIM + d) * C_DIM) * H_DIM + h) * W_DIM;
    const long long c_stride = (long long)H_DIM * W_DIM;      // stride between channels
    float* const obase = out + (long long)b * C_DIM * (NX * NY);

    const int total = C_DIM * W_DIM;   // 7040
    for (int idx = t; idx < total; idx += blockDim.x) {
        const int c = idx / W_DIM;
        const int w = idx - c * W_DIM;
        const int flat = s_flat[w];
        if (flat >= 0) {
            const float v = __ldg(&x[x_base + (long long)c * c_stride + w]);
            atomicAdd(&obase[(long long)c * (NX * NY) + flat], v);
        }
    }
}

extern "C" void kernel_launch(void* const* d_in, const int* in_sizes, int n_in,
                              void* d_out, int out_size) {
    const float* geom = (const float*)d_in[0];   // (8,40,32,88,3)
    const float* x    = (const float*)d_in[1];   // (8,40,80,32,88)
    float* out        = (float*)d_out;           // (8,80,256,256)

    // Zero output (out_size = 8*80*256*256 = 41,943,040 floats, /4 = 10,485,760 float4)
    const int n4 = out_size / 4;
    zero_kernel<<<(n4 + 255) / 256, 256>>>((float4*)d_out, n4);

    // Scatter: one block per (b,d,h)
    const int nblocks = B_DIM * D_DIM * H_DIM;   // 10240
    scatter_kernel<<<nblocks, 256>>>(geom, x, out);
}

// round 3
// speedup vs baseline: 1.4344x; 1.4344x over previous
#include <cuda_runtime.h>

// Problem constants
#define B_DIM 8
#define D_DIM 40
#define H_DIM 32
#define W_DIM 88
#define C_DIM 80
#define NX 256
#define NY 256
#define NCELL (NX * NY)          // 65536 cells per batch
// NZ = 1

// Channel-contiguous scratch accumulator: (B, NCELL, C) fp32 = 168 MB.
// __device__ global (zero-init .bss) — no dynamic allocation.
__device__ float g_scratch[(long long)B_DIM * NCELL * C_DIM];

// ---------------------------------------------------------------------------
// Zero the scratch accumulator every launch (graph replays accumulate otherwise).
// ---------------------------------------------------------------------------
__global__ void zero_scratch_kernel(int n4) {
    int i = blockIdx.x * blockDim.x + threadIdx.x;
    if (i < n4) ((float4*)g_scratch)[i] = make_float4(0.f, 0.f, 0.f, 0.f);
}

// ---------------------------------------------------------------------------
// Scatter: one block per (b, d, h) row of W=88 points.
// Phase 1: threads 0..87 compute flat cell index (or -1) into smem.
// Phase 2: loop over (channel-quad q=0..19, w=0..87); 4 coalesced x loads
//          per item, one red.global.add.v4.f32 into scratch[b][flat][4q..4q+3].
// ---------------------------------------------------------------------------
__global__ void __launch_bounds__(256) scatter_kernel(
    const float* __restrict__ geom,   // (B, D, H, W, 3)
    const float* __restrict__ x)      // (B, D, C, H, W)
{
    __shared__ int s_flat[W_DIM];

    const int bid = blockIdx.x;           // 0 .. B*D*H-1
    const int h   = bid % H_DIM;
    const int bd  = bid / H_DIM;
    const int d   = bd % D_DIM;
    const int b   = bd / D_DIM;

    const int t = threadIdx.x;

    if (t < W_DIM) {
        const float* g = geom + ((long long)bid * W_DIM + t) * 3;
        const float gx = g[0];
        const float gy = g[1];
        const float gz = g[2];

        int flat = -1;
        if (gx >= -51.2f && gx < 51.2f &&
            gy >= -51.2f && gy < 51.2f &&
            gz >= -10.0f && gz < 10.0f) {
            // Match XLA: div-by-const lowered to mul-by-reciprocal (1/0.4 == 2.5f
            // exactly). add-then-mul cannot be FMA-contracted.
            const float rx = (gx + 51.2f) * 2.5f;
            const float ry = (gy + 51.2f) * 2.5f;
            int ix = (int)rx;
            int iy = (int)ry;
            ix = min(max(ix, 0), NX - 1);
            iy = min(max(iy, 0), NY - 1);
            flat = ix * NY + iy;
        }
        s_flat[t] = flat;
    }
    __syncthreads();

    // x index: (((b*D+d)*C + c)*H + h)*W + w  = base + c*(H*W) + w
    const long long x_base = ((long long)(b * D_DIM + d) * C_DIM * H_DIM + h) * W_DIM;
    const int c_stride = H_DIM * W_DIM;                       // 2816
    float* const sb = g_scratch + (long long)b * NCELL * C_DIM;

    const int total = (C_DIM / 4) * W_DIM;   // 20 * 88 = 1760
    for (int idx = t; idx < total; idx += blockDim.x) {
        const int q = idx / W_DIM;           // channel quad 0..19
        const int w = idx - q * W_DIM;
        const int flat = s_flat[w];
        if (flat >= 0) {
            const float* xp = x + x_base + (long long)(q * 4) * c_stride + w;
            float v0 = __ldg(xp);
            float v1 = __ldg(xp + c_stride);
            float v2 = __ldg(xp + 2 * c_stride);
            float v3 = __ldg(xp + 3 * c_stride);
            float* dst = sb + (long long)flat * C_DIM + q * 4;  // 16B aligned
            asm volatile("red.global.add.v4.f32 [%0], {%1, %2, %3, %4};"
                         :: "l"(dst), "f"(v0), "f"(v1), "f"(v2), "f"(v3)
                         : "memory");
        }
    }
}

// ---------------------------------------------------------------------------
// Transpose scratch (B, NCELL, C) -> out (B, C, NCELL) via smem tiles.
// 64 cells x 80 channels per block; float4 coalesced on both sides.
// Writes every output element, so no separate out-zeroing is needed.
// ---------------------------------------------------------------------------
__global__ void __launch_bounds__(256) transpose_kernel(float* __restrict__ out)
{
    __shared__ float tile[64][81];   // pad 81: 2-way worst-case conflicts

    const int blk   = blockIdx.x;            // 0 .. B*1024-1
    const int b     = blk >> 10;
    const int tile0 = (blk & 1023) * 64;     // first cell of tile
    const int t     = threadIdx.x;

    const float4* src = (const float4*)(g_scratch +
                        ((long long)b * NCELL + tile0) * C_DIM);

    // Load: 64 cells * 20 float4 = 1280 vec loads, coalesced.
    #pragma unroll
    for (int i = t; i < 64 * 20; i += 256) {
        const int cell = i / 20;
        const int q    = i - cell * 20;
        float4 v = src[i];
        tile[cell][q * 4 + 0] = v.x;
        tile[cell][q * 4 + 1] = v.y;
        tile[cell][q * 4 + 2] = v.z;
        tile[cell][q * 4 + 3] = v.w;
    }
    __syncthreads();

    // Store: 80 channels * 16 cell-quads = 1280 vec stores, coalesced.
    float* ob = out + (long long)b * C_DIM * NCELL + tile0;
    #pragma unroll
    for (int i = t; i < 80 * 16; i += 256) {
        const int c  = i / 16;
        const int cg = i - c * 16;
        float4 v;
        v.x = tile[cg * 4 + 0][c];
        v.y = tile[cg * 4 + 1][c];
        v.z = tile[cg * 4 + 2][c];
        v.w = tile[cg * 4 + 3][c];
        *(float4*)(ob + (long long)c * NCELL + cg * 4) = v;
    }
}

extern "C" void kernel_launch(void* const* d_in, const int* in_sizes, int n_in,
                              void* d_out, int out_size) {
    const float* geom = (const float*)d_in[0];   // (8,40,32,88,3)
    const float* x    = (const float*)d_in[1];   // (8,40,80,32,88)
    float* out        = (float*)d_out;           // (8,80,256,256)

    // 1) zero scratch (41,943,040 floats -> 10,485,760 float4)
    const int n4 = (B_DIM * NCELL * C_DIM) / 4;
    zero_scratch_kernel<<<(n4 + 255) / 256, 256>>>(n4);

    // 2) scatter with vectorized reductions
    scatter_kernel<<<B_DIM * D_DIM * H_DIM, 256>>>(geom, x);

    // 3) transpose scratch -> out (writes all elements)
    transpose_kernel<<<B_DIM * (NCELL / 64), 256>>>(out);
}